// round 13
// baseline (speedup 1.0000x reference)
#include <cuda_runtime.h>
#include <math.h>

#define BN    2048
#define CIN   256
#define NHID  512
#define NF    112
#define KC    112
#define NL    50
#define MC    100
#define NOUTC 200

// ---------------- scratch (device globals; no allocation) ----------------
__device__ float g_h0[BN * NHID];
__device__ float g_h1[BN * NHID];
__device__ float g_inter[BN * NF];
__device__ float g_base[(size_t)KC * BN * NL];           // 45.9 MB
__device__ __align__(16) unsigned g_cbits[BN * MC * 4];  // packed c_hard bits (for head)
__device__ unsigned g_keys[KC * 2];

// ---------------- Threefry-2x32 (matches JAX) ----------------
__device__ __forceinline__ void tf2x32(unsigned k0, unsigned k1,
                                       unsigned c0, unsigned c1,
                                       unsigned& o0, unsigned& o1) {
    unsigned ks2 = 0x1BD11BDAu ^ k0 ^ k1;
    unsigned x0 = c0 + k0, x1 = c1 + k1;
#define TF_R(r) { x0 += x1; x1 = (x1 << (r)) | (x1 >> (32 - (r))); x1 ^= x0; }
    TF_R(13) TF_R(15) TF_R(26) TF_R(6)
    x0 += k1;  x1 += ks2 + 1u;
    TF_R(17) TF_R(29) TF_R(16) TF_R(24)
    x0 += ks2; x1 += k0 + 2u;
    TF_R(13) TF_R(15) TF_R(26) TF_R(6)
    x0 += k0;  x1 += k1 + 3u;
    TF_R(17) TF_R(29) TF_R(16) TF_R(24)
    x0 += k1;  x1 += ks2 + 4u;
    TF_R(13) TF_R(15) TF_R(26) TF_R(6)
    x0 += ks2; x1 += k0 + 5u;
#undef TF_R
    o0 = x0; o1 = x1;
}

__device__ __forceinline__ float jax_uniform(unsigned k0, unsigned k1, unsigned t) {
    unsigned o0, o1, bits;
    tf2x32(k0, k1, 0u, t, o0, o1); bits = o0 ^ o1;
    return __uint_as_float((bits >> 9) | 0x3F800000u) - 1.0f;
}

// ---------------- init: derive 112 subkeys ----------------
__global__ void init_kernel() {
    if (blockIdx.x == 0 && threadIdx.x == 0) {
        unsigned k0 = 0u, k1 = 42u;            // jax.random.key(42)
        for (int i = 0; i < KC; i++) {
            unsigned n0, n1, s0, s1;
            tf2x32(k0, k1, 0u, 0u, n0, n1);    // new key
            tf2x32(k0, k1, 0u, 1u, s0, s1);    // subkey
            g_keys[2 * i] = s0; g_keys[2 * i + 1] = s1;
            k0 = n0; k1 = n1;
        }
    }
}

// ---- 64x64x16 double-buffered SGEMM, LDS.128 inner loads, exact fmaf k-order ----
__global__ void __launch_bounds__(256) sgemm_v2(
    const float* __restrict__ A, const float* __restrict__ Bm,
    const float* __restrict__ bias, float* __restrict__ C,
    int M, int N, int Kd, int act,
    long sB, long sBias, long sC)
{
    Bm   += (size_t)blockIdx.z * sB;
    bias += (size_t)blockIdx.z * sBias;
    C    += (size_t)blockIdx.z * sC;

    __shared__ __align__(16) float As[2][16][68];
    __shared__ __align__(16) float Bs[2][16][68];
    const int bm = blockIdx.y * 64;
    const int bn = blockIdx.x * 64;
    const int tid = threadIdx.x;
    const int tr = tid / 16, tc = tid % 16;

    float acc[4][4];
#pragma unroll
    for (int i = 0; i < 4; i++)
#pragma unroll
        for (int j = 0; j < 4; j++) acc[i][j] = 0.f;

    const int nk = Kd / 16;
#pragma unroll
    for (int u = 0; u < 4; u++) {
        int l = tid + 256 * u; int m = l >> 4, k = l & 15;
        As[0][k][m] = A[(size_t)(bm + m) * Kd + k];
    }
#pragma unroll
    for (int u = 0; u < 4; u++) {
        int l = tid + 256 * u; int k = l >> 6, n = l & 63;
        Bs[0][k][n] = (bn + n < N) ? Bm[(size_t)k * N + bn + n] : 0.f;
    }
    __syncthreads();

    for (int t = 0; t < nk; t++) {
        const int cur = t & 1, nxt = cur ^ 1;
        float ra[4], rb[4];
        if (t + 1 < nk) {
            const int k0n = (t + 1) * 16;
#pragma unroll
            for (int u = 0; u < 4; u++) {
                int l = tid + 256 * u; int m = l >> 4, k = l & 15;
                ra[u] = A[(size_t)(bm + m) * Kd + k0n + k];
            }
#pragma unroll
            for (int u = 0; u < 4; u++) {
                int l = tid + 256 * u; int k = l >> 6, n = l & 63;
                rb[u] = (bn + n < N) ? Bm[(size_t)(k0n + k) * N + bn + n] : 0.f;
            }
        }
#pragma unroll
        for (int k = 0; k < 16; k++) {
            const float4 a4 = *(const float4*)&As[cur][k][tr * 4];
            const float4 b4 = *(const float4*)&Bs[cur][k][tc * 4];
            float a[4] = {a4.x, a4.y, a4.z, a4.w};
            float b[4] = {b4.x, b4.y, b4.z, b4.w};
#pragma unroll
            for (int i = 0; i < 4; i++)
#pragma unroll
                for (int j = 0; j < 4; j++)
                    acc[i][j] = fmaf(a[i], b[j], acc[i][j]);
        }
        if (t + 1 < nk) {
#pragma unroll
            for (int u = 0; u < 4; u++) {
                int l = tid + 256 * u; int m = l >> 4, k = l & 15;
                As[nxt][k][m] = ra[u];
            }
#pragma unroll
            for (int u = 0; u < 4; u++) {
                int l = tid + 256 * u; int k = l >> 6, n = l & 63;
                Bs[nxt][k][n] = rb[u];
            }
        }
        __syncthreads();
    }
#pragma unroll
    for (int i = 0; i < 4; i++) {
        int m = bm + tr * 4 + i;
#pragma unroll
        for (int j = 0; j < 4; j++) {
            int n = bn + tc * 4 + j;
            if (n < N) {
                float v = acc[i][j] + bias[n];
                if (act) v = (v > 0.f) ? v : 0.01f * v;
                C[(size_t)m * N + n] = v;
            }
        }
    }
}

// Per-q predicated add: hp_a/hp_b += wx/wy iff bit != 0. Bit-exact vs
// fmaf(c,w,hp) with c in {0,1}. add.rn.f32x2 has 2 register-pair operands
// -> RF-bank rt=2 (vs rt=3 for 3-operand FFMA2). No operand staging arrays.
#define QADD(hA, hB, wx, wy, bit)                                       \
    asm("{\n\t.reg .pred p;\n\tsetp.ne.u32 p, %2, 0;\n\t"               \
        "@p add.rn.f32x2 %0, %0, %3;\n\t"                               \
        "@p add.rn.f32x2 %1, %1, %4;\n\t}"                              \
        : "+l"(hA), "+l"(hB)                                            \
        : "r"(bit), "l"(wx), "l"(wy))

// ---------------- ALL 112 concept steps in ONE kernel (R9 structure) ----------------
__global__ void __launch_bounds__(128) steps_fused(
    const float* __restrict__ pW1, const float* __restrict__ pW2,
    const float* __restrict__ pb2,
    float* __restrict__ c_prob, float* __restrict__ c_hard)
{
    __shared__ __align__(16) float baseS[4][52];
    __shared__ float W2S[52];
    __shared__ float b2s;
    __shared__ unsigned keyS[KC * 2];
    __shared__ __align__(16) float Ws[(KC - 1) * 52];   // up to 111 rows x 52

    const int tid  = threadIdx.x;
    const int idx0 = blockIdx.x * 256;
    const int b0   = idx0 / MC;
    const int p0   = idx0 + 2 * tid;
    const int p1   = p0 + 1;
    const int b_0 = p0 / MC, m_0 = p0 - b_0 * MC;
    const int b_1 = p1 / MC, m_1 = p1 - b_1 * MC;
    const int db0 = b_0 - b0, db1 = b_1 - b0;

    for (int l = tid; l < KC * 2; l += 128) keyS[l] = g_keys[l];

    unsigned cb0[4] = {0u, 0u, 0u, 0u};
    unsigned cb1[4] = {0u, 0u, 0u, 0u};

    for (int i = 0; i < KC; i++) {
        // ---- stage step-i data (identical to R9) ----
        for (int l = tid; l < 4 * 52; l += 128) {
            int d = l / 52, h = l - d * 52;
            int bb = b0 + d; if (bb > BN - 1) bb = BN - 1;
            baseS[d][h] = (h < NL) ? g_base[((size_t)i * BN + bb) * NL + h] : 0.f;
        }
        if (tid < 52) W2S[tid] = (tid < NL) ? pW2[i * NL + tid] : 0.f;
        if (tid == 0) b2s = pb2[i];
        for (int l = tid; l < i * 52; l += 128) {
            int j = l / 52, h = l - j * 52;
            Ws[l] = (h < NL) ? pW1[((size_t)i * (NF + KC) + NF + j) * NL + h] : 0.f;
        }
        __syncthreads();

        // ---- recurrence: R9 structure, FFMA2 -> setp + predicated add.rn.f32x2 ----
        unsigned long long hp0[26], hp1[26];
        {
            const unsigned long long* s0 = (const unsigned long long*)(&baseS[db0][0]);
            const unsigned long long* s1 = (const unsigned long long*)(&baseS[db1][0]);
#pragma unroll
            for (int r = 0; r < 26; r++) { hp0[r] = s0[r]; hp1[r] = s1[r]; }
        }

#pragma unroll
        for (int w = 0; w < 4; w++) {
            const int jrem = i - w * 32;
            if (jrem <= 0) break;
            const int jend = (jrem < 32) ? jrem : 32;
            unsigned bw0 = cb0[w];
            unsigned bw1 = cb1[w];
            const float* wrow = Ws + (size_t)w * 32 * 52;
            for (int j2 = 0; j2 < jend; j2++) {
                unsigned bit0 = bw0 & 1u; bw0 >>= 1;
                unsigned bit1 = bw1 & 1u; bw1 >>= 1;
                const ulonglong2* wr = (const ulonglong2*)(wrow + j2 * 52);
#pragma unroll
                for (int q = 0; q < 13; q++) {
                    ulonglong2 wv = wr[q];
                    QADD(hp0[2*q], hp0[2*q+1], wv.x, wv.y, bit0);
                    QADD(hp1[2*q], hp1[2*q+1], wv.x, wv.y, bit1);
                }
            }
        }

        // ---- epilogue: leaky + dot with W2 (exact R9 order) ----
        float z0 = 0.f, z1 = 0.f;
#pragma unroll
        for (int r = 0; r < 25; r++) {
            unsigned lo, hi;
            asm("mov.b64 {%0, %1}, %2;" : "=r"(lo), "=r"(hi) : "l"(hp0[r]));
            float v = __uint_as_float(lo); v = (v > 0.f) ? v : 0.01f * v; z0 = fmaf(v, W2S[2*r],   z0);
            v = __uint_as_float(hi);       v = (v > 0.f) ? v : 0.01f * v; z0 = fmaf(v, W2S[2*r+1], z0);
            asm("mov.b64 {%0, %1}, %2;" : "=r"(lo), "=r"(hi) : "l"(hp1[r]));
            v = __uint_as_float(lo);       v = (v > 0.f) ? v : 0.01f * v; z1 = fmaf(v, W2S[2*r],   z1);
            v = __uint_as_float(hi);       v = (v > 0.f) ? v : 0.01f * v; z1 = fmaf(v, W2S[2*r+1], z1);
        }
        z0 += b2s; z1 += b2s;
        float pp0 = 1.f / (1.f + expf(-z0));
        float pp1 = 1.f / (1.f + expf(-z1));

        const unsigned key0 = keyS[2 * i], key1 = keyS[2 * i + 1];
        unsigned s0 = (jax_uniform(key0, key1, (unsigned)p0) < pp0) ? 1u : 0u;
        unsigned s1 = (jax_uniform(key0, key1, (unsigned)p1) < pp1) ? 1u : 0u;

        const size_t o0 = ((size_t)b_0 * KC + i) * MC + m_0;
        const size_t o1 = ((size_t)b_1 * KC + i) * MC + m_1;
        c_prob[o0] = pp0; c_hard[o0] = (float)s0;
        c_prob[o1] = pp1; c_hard[o1] = (float)s1;

        const int wi = i >> 5; const unsigned sh = (unsigned)(i & 31);
#pragma unroll
        for (int w = 0; w < 4; w++)
            if (w == wi) { cb0[w] |= (s0 << sh); cb1[w] |= (s1 << sh); }

        __syncthreads();   // protect smem before next step's staging
    }

    // publish packed bits for the head
    ((uint4*)g_cbits)[p0] = make_uint4(cb0[0], cb0[1], cb0[2], cb0[3]);
    ((uint4*)g_cbits)[p1] = make_uint4(cb1[0], cb1[1], cb1[2], cb1[3]);
}

// ---------------- fused head (R8-proven) ----------------
#define HEAD_ROW 256
#define HEAD_SMEM (112 * HEAD_ROW * 4 + 400 * 4 + 8 * 128 * 8)
__global__ void __launch_bounds__(256) head_fused(
    const float* __restrict__ hW, const float* __restrict__ hb,
    float* __restrict__ yp)
{
    extern __shared__ __align__(16) float hsm[];
    float*    Wsh   = hsm;                                    // 112 x 256
    unsigned* bitsS = (unsigned*)(hsm + 112 * HEAD_ROW);      // 100 x 4
    unsigned long long* psum = (unsigned long long*)(bitsS + 400);  // 8 warps x 128

    const int b = blockIdx.x, tid = threadIdx.x;
    const int w = tid >> 5, lane = tid & 31;

    for (int l = tid; l < 112 * 50; l += 256) {
        int k = l / 50, q = l - k * 50;
        *(float4*)&Wsh[k * HEAD_ROW + 4 * q] = *(const float4*)&hW[k * 200 + 4 * q];
    }
    for (int l = tid; l < 112 * 14; l += 256) {
        int k = l / 14, q = l - k * 14;
        *(float4*)&Wsh[k * HEAD_ROW + 200 + 4 * q] = make_float4(0.f, 0.f, 0.f, 0.f);
    }
    for (int l = tid; l < 400; l += 256)
        bitsS[l] = g_cbits[(size_t)b * 400 + l];
    __syncthreads();

    unsigned long long zinit[4];
#pragma unroll
    for (int q = 0; q < 4; q++) {
        int o2 = lane + 32 * q;
        float lo = (2 * o2     < NOUTC) ? hb[2 * o2]     : -1e30f;
        float hi = (2 * o2 + 1 < NOUTC) ? hb[2 * o2 + 1] : -1e30f;
        asm("mov.b64 %0, {%1, %2};" : "=l"(zinit[q]) : "r"(__float_as_uint(lo)), "r"(__float_as_uint(hi)));
    }

    float macc[8];
#pragma unroll
    for (int q = 0; q < 8; q++) macc[q] = 0.f;

    for (int m = w; m < MC; m += 8) {
        unsigned long long z2[4];
#pragma unroll
        for (int q = 0; q < 4; q++) z2[q] = zinit[q];

#pragma unroll
        for (int wd = 0; wd < 4; wd++) {
            unsigned bits = bitsS[m * 4 + wd];
            const float* wbase = Wsh + (size_t)wd * 32 * HEAD_ROW;
            while (bits) {
                int t = __ffs(bits) - 1;
                bits &= bits - 1u;
                const unsigned long long* krow =
                    (const unsigned long long*)(wbase + (size_t)t * HEAD_ROW) + lane;
#pragma unroll
                for (int q = 0; q < 4; q++) {
                    asm("add.rn.f32x2 %0, %0, %1;" : "+l"(z2[q]) : "l"(krow[32 * q]));
                }
            }
        }

        float zz[8];
#pragma unroll
        for (int q = 0; q < 4; q++) {
            unsigned lo, hi;
            asm("mov.b64 {%0, %1}, %2;" : "=r"(lo), "=r"(hi) : "l"(z2[q]));
            zz[2 * q] = __uint_as_float(lo); zz[2 * q + 1] = __uint_as_float(hi);
        }
        float mx = zz[0];
#pragma unroll
        for (int q = 1; q < 8; q++) mx = fmaxf(mx, zz[q]);
#pragma unroll
        for (int s = 16; s; s >>= 1) mx = fmaxf(mx, __shfl_xor_sync(0xffffffffu, mx, s));
        float sum = 0.f;
#pragma unroll
        for (int q = 0; q < 8; q++) { zz[q] = expf(zz[q] - mx); sum += zz[q]; }
#pragma unroll
        for (int s = 16; s; s >>= 1) sum += __shfl_xor_sync(0xffffffffu, sum, s);
        float r = 1.f / sum;
#pragma unroll
        for (int q = 0; q < 8; q++) macc[q] = fmaf(zz[q], r, macc[q]);
    }

#pragma unroll
    for (int q = 0; q < 4; q++) {
        unsigned long long pk;
        asm("mov.b64 %0, {%1, %2};" : "=l"(pk)
            : "r"(__float_as_uint(macc[2 * q])), "r"(__float_as_uint(macc[2 * q + 1])));
        psum[w * 128 + lane + 32 * q] = pk;
    }
    __syncthreads();
    if (tid < 100) {
        float slo = 0.f, shi = 0.f;
#pragma unroll
        for (int ww = 0; ww < 8; ww++) {
            unsigned lo, hi;
            asm("mov.b64 {%0, %1}, %2;" : "=r"(lo), "=r"(hi) : "l"(psum[ww * 128 + tid]));
            slo += __uint_as_float(lo); shi += __uint_as_float(hi);
        }
        yp[(size_t)b * NOUTC + 2 * tid]     = logf(slo * (1.f / MC) + 1e-6f);
        yp[(size_t)b * NOUTC + 2 * tid + 1] = logf(shi * (1.f / MC) + 1e-6f);
    }
}

// ---------------- launch ----------------
extern "C" void kernel_launch(void* const* d_in, const int* in_sizes, int n_in,
                              void* d_out, int out_size) {
    const float* x     = (const float*)d_in[0];
    const float* Win   = (const float*)d_in[1];
    const float* binp  = (const float*)d_in[2];
    const float* Wh    = (const float*)d_in[3];
    const float* bh    = (const float*)d_in[4];
    const float* Wout  = (const float*)d_in[5];
    const float* bout  = (const float*)d_in[6];
    const float* pW1   = (const float*)d_in[7];
    const float* pb1   = (const float*)d_in[8];
    const float* pW2   = (const float*)d_in[9];
    const float* pb2   = (const float*)d_in[10];
    const float* hW    = (const float*)d_in[11];
    const float* hb    = (const float*)d_in[12];

    float* out    = (float*)d_out;
    float* c_prob = out;
    float* ypred  = out + (size_t)BN * KC * MC;
    float* c_hard = ypred + (size_t)BN * NOUTC;

    float *h0, *h1, *inter, *base;
    cudaGetSymbolAddress((void**)&h0,    g_h0);
    cudaGetSymbolAddress((void**)&h1,    g_h1);
    cudaGetSymbolAddress((void**)&inter, g_inter);
    cudaGetSymbolAddress((void**)&base,  g_base);

    cudaFuncSetAttribute(head_fused, cudaFuncAttributeMaxDynamicSharedMemorySize, HEAD_SMEM);

    init_kernel<<<1, 32>>>();

    // encoder (LDS.128 db SGEMM; identical fmaf k-order -> bit-identical inter)
    sgemm_v2<<<dim3(NHID/64, BN/64, 1), 256>>>(x,  Win, binp, h0, BN, NHID, CIN,  1, 0,0,0);
    sgemm_v2<<<dim3(NHID/64, BN/64, 1), 256>>>(h0, Wh + 0*NHID*NHID, bh + 0*NHID, h1, BN, NHID, NHID, 1, 0,0,0);
    sgemm_v2<<<dim3(NHID/64, BN/64, 1), 256>>>(h1, Wh + 1*NHID*NHID, bh + 1*NHID, h0, BN, NHID, NHID, 1, 0,0,0);
    sgemm_v2<<<dim3(NHID/64, BN/64, 1), 256>>>(h0, Wh + 2*NHID*NHID, bh + 2*NHID, h1, BN, NHID, NHID, 1, 0,0,0);
    sgemm_v2<<<dim3(NHID/64, BN/64, 1), 256>>>(h1, Wh + 3*NHID*NHID, bh + 3*NHID, h0, BN, NHID, NHID, 1, 0,0,0);
    sgemm_v2<<<dim3(2, BN/64, 1), 256>>>(h0, Wout, bout, inter, BN, NF, NHID, 0, 0,0,0);

    // all base vectors: base[i] = inter @ W1[i][:NF] + b1[i]  (batched over i)
    sgemm_v2<<<dim3(1, BN/64, KC), 256>>>(inter, pW1, pb1, base, BN, NL, NF, 0,
                                          (long)(NF + KC) * NL, NL, (long)BN * NL);

    // all 112 concept steps in one kernel (R9 layout: 2 pairs/thread, 128 threads)
    steps_fused<<<(BN * MC) / 256, 128>>>(pW1, pW2, pb2, c_prob, c_hard);

    // fused head: logits -> softmax -> mean -> log
    head_fused<<<BN, 256, HEAD_SMEM>>>(hW, hb, ypred);
}

// round 14
// speedup vs baseline: 1.4417x; 1.4417x over previous
#include <cuda_runtime.h>
#include <math.h>

#define BN    2048
#define CIN   256
#define NHID  512
#define NF    112
#define KC    112
#define NL    50
#define MC    100
#define NOUTC 200

// ---------------- scratch (device globals; no allocation) ----------------
__device__ float g_h0[BN * NHID];
__device__ float g_h1[BN * NHID];
__device__ float g_inter[BN * NF];
__device__ float g_base[(size_t)KC * BN * NL];           // 45.9 MB
__device__ __align__(16) unsigned g_cbits[BN * MC * 4];  // packed c_hard bits (for head)
__device__ unsigned g_keys[KC * 2];

// ---------------- Threefry-2x32 (matches JAX) ----------------
__device__ __forceinline__ void tf2x32(unsigned k0, unsigned k1,
                                       unsigned c0, unsigned c1,
                                       unsigned& o0, unsigned& o1) {
    unsigned ks2 = 0x1BD11BDAu ^ k0 ^ k1;
    unsigned x0 = c0 + k0, x1 = c1 + k1;
#define TF_R(r) { x0 += x1; x1 = (x1 << (r)) | (x1 >> (32 - (r))); x1 ^= x0; }
    TF_R(13) TF_R(15) TF_R(26) TF_R(6)
    x0 += k1;  x1 += ks2 + 1u;
    TF_R(17) TF_R(29) TF_R(16) TF_R(24)
    x0 += ks2; x1 += k0 + 2u;
    TF_R(13) TF_R(15) TF_R(26) TF_R(6)
    x0 += k0;  x1 += k1 + 3u;
    TF_R(17) TF_R(29) TF_R(16) TF_R(24)
    x0 += k1;  x1 += ks2 + 4u;
    TF_R(13) TF_R(15) TF_R(26) TF_R(6)
    x0 += ks2; x1 += k0 + 5u;
#undef TF_R
    o0 = x0; o1 = x1;
}

__device__ __forceinline__ float jax_uniform(unsigned k0, unsigned k1, unsigned t) {
    unsigned o0, o1, bits;
    tf2x32(k0, k1, 0u, t, o0, o1); bits = o0 ^ o1;
    return __uint_as_float((bits >> 9) | 0x3F800000u) - 1.0f;
}

// ---------------- init: derive 112 subkeys ----------------
__global__ void init_kernel() {
    if (blockIdx.x == 0 && threadIdx.x == 0) {
        unsigned k0 = 0u, k1 = 42u;            // jax.random.key(42)
        for (int i = 0; i < KC; i++) {
            unsigned n0, n1, s0, s1;
            tf2x32(k0, k1, 0u, 0u, n0, n1);    // new key
            tf2x32(k0, k1, 0u, 1u, s0, s1);    // subkey
            g_keys[2 * i] = s0; g_keys[2 * i + 1] = s1;
            k0 = n0; k1 = n1;
        }
    }
}

// ---- 64x64x16 double-buffered SGEMM (kept for the batched base GEMM) ----
__global__ void __launch_bounds__(256) sgemm_v2(
    const float* __restrict__ A, const float* __restrict__ Bm,
    const float* __restrict__ bias, float* __restrict__ C,
    int M, int N, int Kd, int act,
    long sB, long sBias, long sC)
{
    Bm   += (size_t)blockIdx.z * sB;
    bias += (size_t)blockIdx.z * sBias;
    C    += (size_t)blockIdx.z * sC;

    __shared__ __align__(16) float As[2][16][68];
    __shared__ __align__(16) float Bs[2][16][68];
    const int bm = blockIdx.y * 64;
    const int bn = blockIdx.x * 64;
    const int tid = threadIdx.x;
    const int tr = tid / 16, tc = tid % 16;

    float acc[4][4];
#pragma unroll
    for (int i = 0; i < 4; i++)
#pragma unroll
        for (int j = 0; j < 4; j++) acc[i][j] = 0.f;

    const int nk = Kd / 16;
#pragma unroll
    for (int u = 0; u < 4; u++) {
        int l = tid + 256 * u; int m = l >> 4, k = l & 15;
        As[0][k][m] = A[(size_t)(bm + m) * Kd + k];
    }
#pragma unroll
    for (int u = 0; u < 4; u++) {
        int l = tid + 256 * u; int k = l >> 6, n = l & 63;
        Bs[0][k][n] = (bn + n < N) ? Bm[(size_t)k * N + bn + n] : 0.f;
    }
    __syncthreads();

    for (int t = 0; t < nk; t++) {
        const int cur = t & 1, nxt = cur ^ 1;
        float ra[4], rb[4];
        if (t + 1 < nk) {
            const int k0n = (t + 1) * 16;
#pragma unroll
            for (int u = 0; u < 4; u++) {
                int l = tid + 256 * u; int m = l >> 4, k = l & 15;
                ra[u] = A[(size_t)(bm + m) * Kd + k0n + k];
            }
#pragma unroll
            for (int u = 0; u < 4; u++) {
                int l = tid + 256 * u; int k = l >> 6, n = l & 63;
                rb[u] = (bn + n < N) ? Bm[(size_t)(k0n + k) * N + bn + n] : 0.f;
            }
        }
#pragma unroll
        for (int k = 0; k < 16; k++) {
            const float4 a4 = *(const float4*)&As[cur][k][tr * 4];
            const float4 b4 = *(const float4*)&Bs[cur][k][tc * 4];
            float a[4] = {a4.x, a4.y, a4.z, a4.w};
            float b[4] = {b4.x, b4.y, b4.z, b4.w};
#pragma unroll
            for (int i = 0; i < 4; i++)
#pragma unroll
                for (int j = 0; j < 4; j++)
                    acc[i][j] = fmaf(a[i], b[j], acc[i][j]);
        }
        if (t + 1 < nk) {
#pragma unroll
            for (int u = 0; u < 4; u++) {
                int l = tid + 256 * u; int m = l >> 4, k = l & 15;
                As[nxt][k][m] = ra[u];
            }
#pragma unroll
            for (int u = 0; u < 4; u++) {
                int l = tid + 256 * u; int k = l >> 6, n = l & 63;
                Bs[nxt][k][n] = rb[u];
            }
        }
        __syncthreads();
    }
#pragma unroll
    for (int i = 0; i < 4; i++) {
        int m = bm + tr * 4 + i;
#pragma unroll
        for (int j = 0; j < 4; j++) {
            int n = bn + tc * 4 + j;
            if (n < N) {
                float v = acc[i][j] + bias[n];
                if (act) v = (v > 0.f) ? v : 0.01f * v;
                C[(size_t)m * N + n] = v;
            }
        }
    }
}

// ---- 128x64x16 double-buffered SGEMM for the encoder (8x4 microtile).
// Per-output fmaf chain is sequential-k ascending -> bit-identical results;
// only the thread->element mapping changed vs sgemm_v2. M must be mult of 128.
__global__ void __launch_bounds__(256) sgemm_v3(
    const float* __restrict__ A, const float* __restrict__ Bm,
    const float* __restrict__ bias, float* __restrict__ C,
    int M, int N, int Kd, int act)
{
    __shared__ __align__(16) float As[2][16][132];   // 128 + 4 pad
    __shared__ __align__(16) float Bs[2][16][68];
    const int bm = blockIdx.y * 128;
    const int bn = blockIdx.x * 64;
    const int tid = threadIdx.x;
    const int tr = tid / 16, tc = tid % 16;          // tr: 0..15 row-group, tc: 0..15 col-group

    float acc[8][4];
#pragma unroll
    for (int i = 0; i < 8; i++)
#pragma unroll
        for (int j = 0; j < 4; j++) acc[i][j] = 0.f;

    const int nk = Kd / 16;
    // preload tile 0: A 128x16 (8/thread), B 16x64 (4/thread)
#pragma unroll
    for (int u = 0; u < 8; u++) {
        int l = tid + 256 * u; int m = l >> 4, k = l & 15;
        As[0][k][m] = A[(size_t)(bm + m) * Kd + k];
    }
#pragma unroll
    for (int u = 0; u < 4; u++) {
        int l = tid + 256 * u; int k = l >> 6, n = l & 63;
        Bs[0][k][n] = (bn + n < N) ? Bm[(size_t)k * N + bn + n] : 0.f;
    }
    __syncthreads();

    for (int t = 0; t < nk; t++) {
        const int cur = t & 1, nxt = cur ^ 1;
        float ra[8], rb[4];
        if (t + 1 < nk) {
            const int k0n = (t + 1) * 16;
#pragma unroll
            for (int u = 0; u < 8; u++) {
                int l = tid + 256 * u; int m = l >> 4, k = l & 15;
                ra[u] = A[(size_t)(bm + m) * Kd + k0n + k];
            }
#pragma unroll
            for (int u = 0; u < 4; u++) {
                int l = tid + 256 * u; int k = l >> 6, n = l & 63;
                rb[u] = (bn + n < N) ? Bm[(size_t)(k0n + k) * N + bn + n] : 0.f;
            }
        }
#pragma unroll
        for (int k = 0; k < 16; k++) {
            const float4 a4lo = *(const float4*)&As[cur][k][tr * 8];
            const float4 a4hi = *(const float4*)&As[cur][k][tr * 8 + 4];
            const float4 b4   = *(const float4*)&Bs[cur][k][tc * 4];
            float a[8] = {a4lo.x, a4lo.y, a4lo.z, a4lo.w, a4hi.x, a4hi.y, a4hi.z, a4hi.w};
            float b[4] = {b4.x, b4.y, b4.z, b4.w};
#pragma unroll
            for (int i = 0; i < 8; i++)
#pragma unroll
                for (int j = 0; j < 4; j++)
                    acc[i][j] = fmaf(a[i], b[j], acc[i][j]);
        }
        if (t + 1 < nk) {
#pragma unroll
            for (int u = 0; u < 8; u++) {
                int l = tid + 256 * u; int m = l >> 4, k = l & 15;
                As[nxt][k][m] = ra[u];
            }
#pragma unroll
            for (int u = 0; u < 4; u++) {
                int l = tid + 256 * u; int k = l >> 6, n = l & 63;
                Bs[nxt][k][n] = rb[u];
            }
        }
        __syncthreads();
    }
#pragma unroll
    for (int i = 0; i < 8; i++) {
        int m = bm + tr * 8 + i;
#pragma unroll
        for (int j = 0; j < 4; j++) {
            int n = bn + tc * 4 + j;
            if (n < N) {
                float v = acc[i][j] + bias[n];
                if (act) v = (v > 0.f) ? v : 0.01f * v;
                C[(size_t)m * N + n] = v;
            }
        }
    }
}

// ---------------- ALL 112 concept steps in ONE kernel (R9-proven, verbatim) ----------------
__global__ void __launch_bounds__(128) steps_fused(
    const float* __restrict__ pW1, const float* __restrict__ pW2,
    const float* __restrict__ pb2,
    float* __restrict__ c_prob, float* __restrict__ c_hard)
{
    __shared__ __align__(16) float baseS[4][52];
    __shared__ float W2S[52];
    __shared__ float b2s;
    __shared__ unsigned keyS[KC * 2];
    __shared__ __align__(16) float Ws[(KC - 1) * 52];   // up to 111 rows x 52

    const int tid  = threadIdx.x;
    const int idx0 = blockIdx.x * 256;
    const int b0   = idx0 / MC;
    const int p0   = idx0 + 2 * tid;
    const int p1   = p0 + 1;
    const int b_0 = p0 / MC, m_0 = p0 - b_0 * MC;
    const int b_1 = p1 / MC, m_1 = p1 - b_1 * MC;
    const int db0 = b_0 - b0, db1 = b_1 - b0;

    for (int l = tid; l < KC * 2; l += 128) keyS[l] = g_keys[l];

    unsigned cb0[4] = {0u, 0u, 0u, 0u};
    unsigned cb1[4] = {0u, 0u, 0u, 0u};

    for (int i = 0; i < KC; i++) {
        // ---- stage step-i data ----
        for (int l = tid; l < 4 * 52; l += 128) {
            int d = l / 52, h = l - d * 52;
            int bb = b0 + d; if (bb > BN - 1) bb = BN - 1;
            baseS[d][h] = (h < NL) ? g_base[((size_t)i * BN + bb) * NL + h] : 0.f;
        }
        if (tid < 52) W2S[tid] = (tid < NL) ? pW2[i * NL + tid] : 0.f;
        if (tid == 0) b2s = pb2[i];
        for (int l = tid; l < i * 52; l += 128) {
            int j = l / 52, h = l - j * 52;
            Ws[l] = (h < NL) ? pW1[((size_t)i * (NF + KC) + NF + j) * NL + h] : 0.f;
        }
        __syncthreads();

        // ---- R9-exact recurrence body ----
        unsigned long long hp0[26], hp1[26];
        {
            const unsigned long long* s0 = (const unsigned long long*)(&baseS[db0][0]);
            const unsigned long long* s1 = (const unsigned long long*)(&baseS[db1][0]);
#pragma unroll
            for (int r = 0; r < 26; r++) { hp0[r] = s0[r]; hp1[r] = s1[r]; }
        }

#pragma unroll
        for (int w = 0; w < 4; w++) {
            const int jrem = i - w * 32;
            if (jrem <= 0) break;
            const int jend = (jrem < 32) ? jrem : 32;
            unsigned bw0 = cb0[w];
            unsigned bw1 = cb1[w];
            const float* wrow = Ws + (size_t)w * 32 * 52;
            for (int j2 = 0; j2 < jend; j2++) {
                float c0 = (bw0 & 1u) ? 1.f : 0.f; bw0 >>= 1;
                float c1 = (bw1 & 1u) ? 1.f : 0.f; bw1 >>= 1;
                unsigned long long cc0, cc1;
                asm("mov.b64 %0, {%1, %1};" : "=l"(cc0) : "r"(__float_as_uint(c0)));
                asm("mov.b64 %0, {%1, %1};" : "=l"(cc1) : "r"(__float_as_uint(c1)));
                const ulonglong2* wr = (const ulonglong2*)(wrow + j2 * 52);
#pragma unroll
                for (int q = 0; q < 13; q++) {
                    ulonglong2 wv = wr[q];
                    asm("fma.rn.f32x2 %0, %1, %2, %0;" : "+l"(hp0[2*q  ]) : "l"(cc0), "l"(wv.x));
                    asm("fma.rn.f32x2 %0, %1, %2, %0;" : "+l"(hp0[2*q+1]) : "l"(cc0), "l"(wv.y));
                    asm("fma.rn.f32x2 %0, %1, %2, %0;" : "+l"(hp1[2*q  ]) : "l"(cc1), "l"(wv.x));
                    asm("fma.rn.f32x2 %0, %1, %2, %0;" : "+l"(hp1[2*q+1]) : "l"(cc1), "l"(wv.y));
                }
            }
        }

        // ---- epilogue: leaky + dot with W2 (exact order) ----
        float z0 = 0.f, z1 = 0.f;
#pragma unroll
        for (int r = 0; r < 25; r++) {
            unsigned lo, hi;
            asm("mov.b64 {%0, %1}, %2;" : "=r"(lo), "=r"(hi) : "l"(hp0[r]));
            float v = __uint_as_float(lo); v = (v > 0.f) ? v : 0.01f * v; z0 = fmaf(v, W2S[2*r],   z0);
            v = __uint_as_float(hi);       v = (v > 0.f) ? v : 0.01f * v; z0 = fmaf(v, W2S[2*r+1], z0);
            asm("mov.b64 {%0, %1}, %2;" : "=r"(lo), "=r"(hi) : "l"(hp1[r]));
            v = __uint_as_float(lo);       v = (v > 0.f) ? v : 0.01f * v; z1 = fmaf(v, W2S[2*r],   z1);
            v = __uint_as_float(hi);       v = (v > 0.f) ? v : 0.01f * v; z1 = fmaf(v, W2S[2*r+1], z1);
        }
        z0 += b2s; z1 += b2s;
        float pp0 = 1.f / (1.f + expf(-z0));
        float pp1 = 1.f / (1.f + expf(-z1));

        const unsigned key0 = keyS[2 * i], key1 = keyS[2 * i + 1];
        unsigned s0 = (jax_uniform(key0, key1, (unsigned)p0) < pp0) ? 1u : 0u;
        unsigned s1 = (jax_uniform(key0, key1, (unsigned)p1) < pp1) ? 1u : 0u;

        const size_t o0 = ((size_t)b_0 * KC + i) * MC + m_0;
        const size_t o1 = ((size_t)b_1 * KC + i) * MC + m_1;
        c_prob[o0] = pp0; c_hard[o0] = (float)s0;
        c_prob[o1] = pp1; c_hard[o1] = (float)s1;

        const int wi = i >> 5; const unsigned sh = (unsigned)(i & 31);
#pragma unroll
        for (int w = 0; w < 4; w++)
            if (w == wi) { cb0[w] |= (s0 << sh); cb1[w] |= (s1 << sh); }

        __syncthreads();   // protect smem before next step's staging
    }

    // publish packed bits for the head
    ((uint4*)g_cbits)[p0] = make_uint4(cb0[0], cb0[1], cb0[2], cb0[3]);
    ((uint4*)g_cbits)[p1] = make_uint4(cb1[0], cb1[1], cb1[2], cb1[3]);
}

// ---------------- fused head (R8-proven) ----------------
#define HEAD_ROW 256
#define HEAD_SMEM (112 * HEAD_ROW * 4 + 400 * 4 + 8 * 128 * 8)
__global__ void __launch_bounds__(256) head_fused(
    const float* __restrict__ hW, const float* __restrict__ hb,
    float* __restrict__ yp)
{
    extern __shared__ __align__(16) float hsm[];
    float*    Wsh   = hsm;                                    // 112 x 256
    unsigned* bitsS = (unsigned*)(hsm + 112 * HEAD_ROW);      // 100 x 4
    unsigned long long* psum = (unsigned long long*)(bitsS + 400);  // 8 warps x 128

    const int b = blockIdx.x, tid = threadIdx.x;
    const int w = tid >> 5, lane = tid & 31;

    for (int l = tid; l < 112 * 50; l += 256) {
        int k = l / 50, q = l - k * 50;
        *(float4*)&Wsh[k * HEAD_ROW + 4 * q] = *(const float4*)&hW[k * 200 + 4 * q];
    }
    for (int l = tid; l < 112 * 14; l += 256) {
        int k = l / 14, q = l - k * 14;
        *(float4*)&Wsh[k * HEAD_ROW + 200 + 4 * q] = make_float4(0.f, 0.f, 0.f, 0.f);
    }
    for (int l = tid; l < 400; l += 256)
        bitsS[l] = g_cbits[(size_t)b * 400 + l];
    __syncthreads();

    unsigned long long zinit[4];
#pragma unroll
    for (int q = 0; q < 4; q++) {
        int o2 = lane + 32 * q;
        float lo = (2 * o2     < NOUTC) ? hb[2 * o2]     : -1e30f;
        float hi = (2 * o2 + 1 < NOUTC) ? hb[2 * o2 + 1] : -1e30f;
        asm("mov.b64 %0, {%1, %2};" : "=l"(zinit[q]) : "r"(__float_as_uint(lo)), "r"(__float_as_uint(hi)));
    }

    float macc[8];
#pragma unroll
    for (int q = 0; q < 8; q++) macc[q] = 0.f;

    for (int m = w; m < MC; m += 8) {
        unsigned long long z2[4];
#pragma unroll
        for (int q = 0; q < 4; q++) z2[q] = zinit[q];

#pragma unroll
        for (int wd = 0; wd < 4; wd++) {
            unsigned bits = bitsS[m * 4 + wd];
            const float* wbase = Wsh + (size_t)wd * 32 * HEAD_ROW;
            while (bits) {
                int t = __ffs(bits) - 1;
                bits &= bits - 1u;
                const unsigned long long* krow =
                    (const unsigned long long*)(wbase + (size_t)t * HEAD_ROW) + lane;
#pragma unroll
                for (int q = 0; q < 4; q++) {
                    asm("add.rn.f32x2 %0, %0, %1;" : "+l"(z2[q]) : "l"(krow[32 * q]));
                }
            }
        }

        float zz[8];
#pragma unroll
        for (int q = 0; q < 4; q++) {
            unsigned lo, hi;
            asm("mov.b64 {%0, %1}, %2;" : "=r"(lo), "=r"(hi) : "l"(z2[q]));
            zz[2 * q] = __uint_as_float(lo); zz[2 * q + 1] = __uint_as_float(hi);
        }
        float mx = zz[0];
#pragma unroll
        for (int q = 1; q < 8; q++) mx = fmaxf(mx, zz[q]);
#pragma unroll
        for (int s = 16; s; s >>= 1) mx = fmaxf(mx, __shfl_xor_sync(0xffffffffu, mx, s));
        float sum = 0.f;
#pragma unroll
        for (int q = 0; q < 8; q++) { zz[q] = expf(zz[q] - mx); sum += zz[q]; }
#pragma unroll
        for (int s = 16; s; s >>= 1) sum += __shfl_xor_sync(0xffffffffu, sum, s);
        float r = 1.f / sum;
#pragma unroll
        for (int q = 0; q < 8; q++) macc[q] = fmaf(zz[q], r, macc[q]);
    }

#pragma unroll
    for (int q = 0; q < 4; q++) {
        unsigned long long pk;
        asm("mov.b64 %0, {%1, %2};" : "=l"(pk)
            : "r"(__float_as_uint(macc[2 * q])), "r"(__float_as_uint(macc[2 * q + 1])));
        psum[w * 128 + lane + 32 * q] = pk;
    }
    __syncthreads();
    if (tid < 100) {
        float slo = 0.f, shi = 0.f;
#pragma unroll
        for (int ww = 0; ww < 8; ww++) {
            unsigned lo, hi;
            asm("mov.b64 {%0, %1}, %2;" : "=r"(lo), "=r"(hi) : "l"(psum[ww * 128 + tid]));
            slo += __uint_as_float(lo); shi += __uint_as_float(hi);
        }
        yp[(size_t)b * NOUTC + 2 * tid]     = logf(slo * (1.f / MC) + 1e-6f);
        yp[(size_t)b * NOUTC + 2 * tid + 1] = logf(shi * (1.f / MC) + 1e-6f);
    }
}

// ---------------- launch ----------------
extern "C" void kernel_launch(void* const* d_in, const int* in_sizes, int n_in,
                              void* d_out, int out_size) {
    const float* x     = (const float*)d_in[0];
    const float* Win   = (const float*)d_in[1];
    const float* binp  = (const float*)d_in[2];
    const float* Wh    = (const float*)d_in[3];
    const float* bh    = (const float*)d_in[4];
    const float* Wout  = (const float*)d_in[5];
    const float* bout  = (const float*)d_in[6];
    const float* pW1   = (const float*)d_in[7];
    const float* pb1   = (const float*)d_in[8];
    const float* pW2   = (const float*)d_in[9];
    const float* pb2   = (const float*)d_in[10];
    const float* hW    = (const float*)d_in[11];
    const float* hb    = (const float*)d_in[12];

    float* out    = (float*)d_out;
    float* c_prob = out;
    float* ypred  = out + (size_t)BN * KC * MC;
    float* c_hard = ypred + (size_t)BN * NOUTC;

    float *h0, *h1, *inter, *base;
    cudaGetSymbolAddress((void**)&h0,    g_h0);
    cudaGetSymbolAddress((void**)&h1,    g_h1);
    cudaGetSymbolAddress((void**)&inter, g_inter);
    cudaGetSymbolAddress((void**)&base,  g_base);

    cudaFuncSetAttribute(head_fused, cudaFuncAttributeMaxDynamicSharedMemorySize, HEAD_SMEM);

    init_kernel<<<1, 32>>>();

    // encoder: 128x64 tiles (bit-identical per-element fmaf k-chain)
    sgemm_v3<<<dim3(NHID/64, BN/128, 1), 256>>>(x,  Win, binp, h0, BN, NHID, CIN,  1);
    sgemm_v3<<<dim3(NHID/64, BN/128, 1), 256>>>(h0, Wh + 0*NHID*NHID, bh + 0*NHID, h1, BN, NHID, NHID, 1);
    sgemm_v3<<<dim3(NHID/64, BN/128, 1), 256>>>(h1, Wh + 1*NHID*NHID, bh + 1*NHID, h0, BN, NHID, NHID, 1);
    sgemm_v3<<<dim3(NHID/64, BN/128, 1), 256>>>(h0, Wh + 2*NHID*NHID, bh + 2*NHID, h1, BN, NHID, NHID, 1);
    sgemm_v3<<<dim3(NHID/64, BN/128, 1), 256>>>(h1, Wh + 3*NHID*NHID, bh + 3*NHID, h0, BN, NHID, NHID, 1);
    sgemm_v3<<<dim3(2, BN/128, 1), 256>>>(h0, Wout, bout, inter, BN, NF, NHID, 0);

    // all base vectors: base[i] = inter @ W1[i][:NF] + b1[i]  (batched over i)
    sgemm_v2<<<dim3(1, BN/64, KC), 256>>>(inter, pW1, pb1, base, BN, NL, NF, 0,
                                          (long)(NF + KC) * NL, NL, (long)BN * NL);

    // all 112 concept steps in one kernel (R9-proven body)
    steps_fused<<<(BN * MC) / 256, 128>>>(pW1, pW2, pb2, c_prob, c_hard);

    // fused head: logits -> softmax -> mean -> log
    head_fused<<<BN, 256, HEAD_SMEM>>>(hW, hb, ypred);
}

// round 15
// speedup vs baseline: 1.5481x; 1.0738x over previous
#include <cuda_runtime.h>
#include <math.h>

#define BN    2048
#define CIN   256
#define NHID  512
#define NF    112
#define KC    112
#define NL    50
#define MC    100
#define NOUTC 200

// ---------------- scratch (device globals; no allocation) ----------------
__device__ float g_h0[BN * NHID];
__device__ float g_h1[BN * NHID];
__device__ float g_inter[BN * NF];
__device__ float g_base[(size_t)KC * BN * NL];           // 45.9 MB
__device__ __align__(16) unsigned g_cbits[BN * MC * 4];  // packed c_hard bits (for head)
__device__ unsigned g_keys[KC * 2];

// ---------------- Threefry-2x32 (matches JAX) ----------------
__device__ __forceinline__ void tf2x32(unsigned k0, unsigned k1,
                                       unsigned c0, unsigned c1,
                                       unsigned& o0, unsigned& o1) {
    unsigned ks2 = 0x1BD11BDAu ^ k0 ^ k1;
    unsigned x0 = c0 + k0, x1 = c1 + k1;
#define TF_R(r) { x0 += x1; x1 = (x1 << (r)) | (x1 >> (32 - (r))); x1 ^= x0; }
    TF_R(13) TF_R(15) TF_R(26) TF_R(6)
    x0 += k1;  x1 += ks2 + 1u;
    TF_R(17) TF_R(29) TF_R(16) TF_R(24)
    x0 += ks2; x1 += k0 + 2u;
    TF_R(13) TF_R(15) TF_R(26) TF_R(6)
    x0 += k0;  x1 += k1 + 3u;
    TF_R(17) TF_R(29) TF_R(16) TF_R(24)
    x0 += k1;  x1 += ks2 + 4u;
    TF_R(13) TF_R(15) TF_R(26) TF_R(6)
    x0 += ks2; x1 += k0 + 5u;
#undef TF_R
    o0 = x0; o1 = x1;
}

__device__ __forceinline__ float jax_uniform(unsigned k0, unsigned k1, unsigned t) {
    unsigned o0, o1, bits;
    tf2x32(k0, k1, 0u, t, o0, o1); bits = o0 ^ o1;
    return __uint_as_float((bits >> 9) | 0x3F800000u) - 1.0f;
}

// ---------------- init: derive 112 subkeys ----------------
__global__ void init_kernel() {
    if (blockIdx.x == 0 && threadIdx.x == 0) {
        unsigned k0 = 0u, k1 = 42u;            // jax.random.key(42)
        for (int i = 0; i < KC; i++) {
            unsigned n0, n1, s0, s1;
            tf2x32(k0, k1, 0u, 0u, n0, n1);    // new key
            tf2x32(k0, k1, 0u, 1u, s0, s1);    // subkey
            g_keys[2 * i] = s0; g_keys[2 * i + 1] = s1;
            k0 = n0; k1 = n1;
        }
    }
}

// ---- 64x64x16 double-buffered SGEMM (kept for the batched base GEMM) ----
__global__ void __launch_bounds__(256) sgemm_v2(
    const float* __restrict__ A, const float* __restrict__ Bm,
    const float* __restrict__ bias, float* __restrict__ C,
    int M, int N, int Kd, int act,
    long sB, long sBias, long sC)
{
    Bm   += (size_t)blockIdx.z * sB;
    bias += (size_t)blockIdx.z * sBias;
    C    += (size_t)blockIdx.z * sC;

    __shared__ __align__(16) float As[2][16][68];
    __shared__ __align__(16) float Bs[2][16][68];
    const int bm = blockIdx.y * 64;
    const int bn = blockIdx.x * 64;
    const int tid = threadIdx.x;
    const int tr = tid / 16, tc = tid % 16;

    float acc[4][4];
#pragma unroll
    for (int i = 0; i < 4; i++)
#pragma unroll
        for (int j = 0; j < 4; j++) acc[i][j] = 0.f;

    const int nk = Kd / 16;
#pragma unroll
    for (int u = 0; u < 4; u++) {
        int l = tid + 256 * u; int m = l >> 4, k = l & 15;
        As[0][k][m] = A[(size_t)(bm + m) * Kd + k];
    }
#pragma unroll
    for (int u = 0; u < 4; u++) {
        int l = tid + 256 * u; int k = l >> 6, n = l & 63;
        Bs[0][k][n] = (bn + n < N) ? Bm[(size_t)k * N + bn + n] : 0.f;
    }
    __syncthreads();

    for (int t = 0; t < nk; t++) {
        const int cur = t & 1, nxt = cur ^ 1;
        float ra[4], rb[4];
        if (t + 1 < nk) {
            const int k0n = (t + 1) * 16;
#pragma unroll
            for (int u = 0; u < 4; u++) {
                int l = tid + 256 * u; int m = l >> 4, k = l & 15;
                ra[u] = A[(size_t)(bm + m) * Kd + k0n + k];
            }
#pragma unroll
            for (int u = 0; u < 4; u++) {
                int l = tid + 256 * u; int k = l >> 6, n = l & 63;
                rb[u] = (bn + n < N) ? Bm[(size_t)(k0n + k) * N + bn + n] : 0.f;
            }
        }
#pragma unroll
        for (int k = 0; k < 16; k++) {
            const float4 a4 = *(const float4*)&As[cur][k][tr * 4];
            const float4 b4 = *(const float4*)&Bs[cur][k][tc * 4];
            float a[4] = {a4.x, a4.y, a4.z, a4.w};
            float b[4] = {b4.x, b4.y, b4.z, b4.w};
#pragma unroll
            for (int i = 0; i < 4; i++)
#pragma unroll
                for (int j = 0; j < 4; j++)
                    acc[i][j] = fmaf(a[i], b[j], acc[i][j]);
        }
        if (t + 1 < nk) {
#pragma unroll
            for (int u = 0; u < 4; u++) {
                int l = tid + 256 * u; int m = l >> 4, k = l & 15;
                As[nxt][k][m] = ra[u];
            }
#pragma unroll
            for (int u = 0; u < 4; u++) {
                int l = tid + 256 * u; int k = l >> 6, n = l & 63;
                Bs[nxt][k][n] = rb[u];
            }
        }
        __syncthreads();
    }
#pragma unroll
    for (int i = 0; i < 4; i++) {
        int m = bm + tr * 4 + i;
#pragma unroll
        for (int j = 0; j < 4; j++) {
            int n = bn + tc * 4 + j;
            if (n < N) {
                float v = acc[i][j] + bias[n];
                if (act) v = (v > 0.f) ? v : 0.01f * v;
                C[(size_t)m * N + n] = v;
            }
        }
    }
}

// ---- 128x64x16 double-buffered SGEMM for the encoder (8x4 microtile) ----
__global__ void __launch_bounds__(256) sgemm_v3(
    const float* __restrict__ A, const float* __restrict__ Bm,
    const float* __restrict__ bias, float* __restrict__ C,
    int M, int N, int Kd, int act)
{
    __shared__ __align__(16) float As[2][16][132];   // 128 + 4 pad
    __shared__ __align__(16) float Bs[2][16][68];
    const int bm = blockIdx.y * 128;
    const int bn = blockIdx.x * 64;
    const int tid = threadIdx.x;
    const int tr = tid / 16, tc = tid % 16;

    float acc[8][4];
#pragma unroll
    for (int i = 0; i < 8; i++)
#pragma unroll
        for (int j = 0; j < 4; j++) acc[i][j] = 0.f;

    const int nk = Kd / 16;
#pragma unroll
    for (int u = 0; u < 8; u++) {
        int l = tid + 256 * u; int m = l >> 4, k = l & 15;
        As[0][k][m] = A[(size_t)(bm + m) * Kd + k];
    }
#pragma unroll
    for (int u = 0; u < 4; u++) {
        int l = tid + 256 * u; int k = l >> 6, n = l & 63;
        Bs[0][k][n] = (bn + n < N) ? Bm[(size_t)k * N + bn + n] : 0.f;
    }
    __syncthreads();

    for (int t = 0; t < nk; t++) {
        const int cur = t & 1, nxt = cur ^ 1;
        float ra[8], rb[4];
        if (t + 1 < nk) {
            const int k0n = (t + 1) * 16;
#pragma unroll
            for (int u = 0; u < 8; u++) {
                int l = tid + 256 * u; int m = l >> 4, k = l & 15;
                ra[u] = A[(size_t)(bm + m) * Kd + k0n + k];
            }
#pragma unroll
            for (int u = 0; u < 4; u++) {
                int l = tid + 256 * u; int k = l >> 6, n = l & 63;
                rb[u] = (bn + n < N) ? Bm[(size_t)(k0n + k) * N + bn + n] : 0.f;
            }
        }
#pragma unroll
        for (int k = 0; k < 16; k++) {
            const float4 a4lo = *(const float4*)&As[cur][k][tr * 8];
            const float4 a4hi = *(const float4*)&As[cur][k][tr * 8 + 4];
            const float4 b4   = *(const float4*)&Bs[cur][k][tc * 4];
            float a[8] = {a4lo.x, a4lo.y, a4lo.z, a4lo.w, a4hi.x, a4hi.y, a4hi.z, a4hi.w};
            float b[4] = {b4.x, b4.y, b4.z, b4.w};
#pragma unroll
            for (int i = 0; i < 8; i++)
#pragma unroll
                for (int j = 0; j < 4; j++)
                    acc[i][j] = fmaf(a[i], b[j], acc[i][j]);
        }
        if (t + 1 < nk) {
#pragma unroll
            for (int u = 0; u < 8; u++) {
                int l = tid + 256 * u; int m = l >> 4, k = l & 15;
                As[nxt][k][m] = ra[u];
            }
#pragma unroll
            for (int u = 0; u < 4; u++) {
                int l = tid + 256 * u; int k = l >> 6, n = l & 63;
                Bs[nxt][k][n] = rb[u];
            }
        }
        __syncthreads();
    }
#pragma unroll
    for (int i = 0; i < 8; i++) {
        int m = bm + tr * 8 + i;
#pragma unroll
        for (int j = 0; j < 4; j++) {
            int n = bn + tc * 4 + j;
            if (n < N) {
                float v = acc[i][j] + bias[n];
                if (act) v = (v > 0.f) ? v : 0.01f * v;
                C[(size_t)m * N + n] = v;
            }
        }
    }
}

// One h-half pass over the j history. R0 = first u64 chunk, NQ = ulonglong2
// count (2*NQ u64 chunks), ZR = u64 chunks feeding the z-chain (skips pads).
// OFF is an opaque 0 (see call site) creating a data dependency on the
// previous pass's z so ptxas cannot hoist this pass's hp live ranges.
// Per-element fmaf chains and the z-chain order are IDENTICAL to R9.
#define RUN_PASS(R0, NQ, ZR, OFF)                                               \
{                                                                               \
    unsigned long long hp0[2*(NQ)], hp1[2*(NQ)];                                \
    {                                                                           \
        const unsigned long long* s0 =                                          \
            (const unsigned long long*)(&baseS[db0][0]) + (R0) + (OFF);         \
        const unsigned long long* s1 =                                          \
            (const unsigned long long*)(&baseS[db1][0]) + (R0) + (OFF);         \
        _Pragma("unroll")                                                       \
        for (int r = 0; r < 2*(NQ); r++) { hp0[r] = s0[r]; hp1[r] = s1[r]; }    \
    }                                                                           \
    _Pragma("unroll")                                                           \
    for (int w = 0; w < 4; w++) {                                               \
        const int jrem = i - w * 32;                                            \
        if (jrem <= 0) break;                                                   \
        const int jend = (jrem < 32) ? jrem : 32;                               \
        unsigned bw0 = cb0[w];                                                  \
        unsigned bw1 = cb1[w];                                                  \
        const float* wrow = Ws + (size_t)w * 32 * 52 + 2 * ((R0) + (OFF));      \
        for (int j2 = 0; j2 < jend; j2++) {                                     \
            float c0 = (bw0 & 1u) ? 1.f : 0.f; bw0 >>= 1;                       \
            float c1 = (bw1 & 1u) ? 1.f : 0.f; bw1 >>= 1;                       \
            unsigned long long cc0, cc1;                                        \
            asm("mov.b64 %0, {%1, %1};" : "=l"(cc0) : "r"(__float_as_uint(c0))); \
            asm("mov.b64 %0, {%1, %1};" : "=l"(cc1) : "r"(__float_as_uint(c1))); \
            const ulonglong2* wr = (const ulonglong2*)(wrow + j2 * 52);         \
            _Pragma("unroll")                                                   \
            for (int q = 0; q < (NQ); q++) {                                    \
                ulonglong2 wv = wr[q];                                          \
                asm("fma.rn.f32x2 %0, %1, %2, %0;" : "+l"(hp0[2*q  ]) : "l"(cc0), "l"(wv.x)); \
                asm("fma.rn.f32x2 %0, %1, %2, %0;" : "+l"(hp0[2*q+1]) : "l"(cc0), "l"(wv.y)); \
                asm("fma.rn.f32x2 %0, %1, %2, %0;" : "+l"(hp1[2*q  ]) : "l"(cc1), "l"(wv.x)); \
                asm("fma.rn.f32x2 %0, %1, %2, %0;" : "+l"(hp1[2*q+1]) : "l"(cc1), "l"(wv.y)); \
            }                                                                   \
        }                                                                       \
    }                                                                           \
    _Pragma("unroll")                                                           \
    for (int r = 0; r < (ZR); r++) {                                            \
        const int gr = (R0) + r;                                                \
        unsigned lo, hi;                                                        \
        asm("mov.b64 {%0, %1}, %2;" : "=r"(lo), "=r"(hi) : "l"(hp0[r]));        \
        float v = __uint_as_float(lo); v = (v > 0.f) ? v : 0.01f * v; z0 = fmaf(v, W2S[2*gr],   z0); \
        v = __uint_as_float(hi);       v = (v > 0.f) ? v : 0.01f * v; z0 = fmaf(v, W2S[2*gr+1], z0); \
        asm("mov.b64 {%0, %1}, %2;" : "=r"(lo), "=r"(hi) : "l"(hp1[r]));        \
        v = __uint_as_float(lo);       v = (v > 0.f) ? v : 0.01f * v; z1 = fmaf(v, W2S[2*gr],   z1); \
        v = __uint_as_float(hi);       v = (v > 0.f) ? v : 0.01f * v; z1 = fmaf(v, W2S[2*gr+1], z1); \
    }                                                                           \
}

// ---------------- ALL 112 concept steps in ONE kernel, two-pass h-split ----------------
__global__ void __launch_bounds__(128) steps_fused(
    const float* __restrict__ pW1, const float* __restrict__ pW2,
    const float* __restrict__ pb2,
    float* __restrict__ c_prob, float* __restrict__ c_hard)
{
    __shared__ __align__(16) float baseS[4][52];
    __shared__ float W2S[52];
    __shared__ float b2s;
    __shared__ unsigned keyS[KC * 2];
    __shared__ __align__(16) float Ws[(KC - 1) * 52];   // up to 111 rows x 52

    const int tid  = threadIdx.x;
    const int idx0 = blockIdx.x * 256;
    const int b0   = idx0 / MC;
    const int p0   = idx0 + 2 * tid;
    const int p1   = p0 + 1;
    const int b_0 = p0 / MC, m_0 = p0 - b_0 * MC;
    const int b_1 = p1 / MC, m_1 = p1 - b_1 * MC;
    const int db0 = b_0 - b0, db1 = b_1 - b0;

    for (int l = tid; l < KC * 2; l += 128) keyS[l] = g_keys[l];

    unsigned cb0[4] = {0u, 0u, 0u, 0u};
    unsigned cb1[4] = {0u, 0u, 0u, 0u};

    for (int i = 0; i < KC; i++) {
        // ---- stage step-i data (identical to R14) ----
        for (int l = tid; l < 4 * 52; l += 128) {
            int d = l / 52, h = l - d * 52;
            int bb = b0 + d; if (bb > BN - 1) bb = BN - 1;
            baseS[d][h] = (h < NL) ? g_base[((size_t)i * BN + bb) * NL + h] : 0.f;
        }
        if (tid < 52) W2S[tid] = (tid < NL) ? pW2[i * NL + tid] : 0.f;
        if (tid == 0) b2s = pb2[i];
        for (int l = tid; l < i * 52; l += 128) {
            int j = l / 52, h = l - j * 52;
            Ws[l] = (h < NL) ? pW1[((size_t)i * (NF + KC) + NF + j) * NL + h] : 0.f;
        }
        __syncthreads();

        // ---- two-pass recurrence + epilogue (bit-exact vs R9) ----
        float z0 = 0.f, z1 = 0.f;

        // pass 0: u64 chunks 0..11 (h 0..23), all feed z
        RUN_PASS(0, 6, 12, 0)

        // opaque zero depending on z0/z1: forces pass-1 hp loads after pass-0
        // epilogue so the two hp live ranges never coexist
        int off2 = 0;
        {
            unsigned dz = __float_as_uint(z0) ^ __float_as_uint(z1);
            asm("" : "+r"(off2) : "r"(dz));
        }

        // pass 1: u64 chunks 12..25 (h 24..51); z uses chunks 12..24 (h 24..49),
        // chunk 25 = zero pads (skipped, exact)
        RUN_PASS(12, 7, 13, off2)

        z0 += b2s; z1 += b2s;
        float pp0 = 1.f / (1.f + expf(-z0));
        float pp1 = 1.f / (1.f + expf(-z1));

        const unsigned key0 = keyS[2 * i], key1 = keyS[2 * i + 1];
        unsigned s0 = (jax_uniform(key0, key1, (unsigned)p0) < pp0) ? 1u : 0u;
        unsigned s1 = (jax_uniform(key0, key1, (unsigned)p1) < pp1) ? 1u : 0u;

        const size_t o0 = ((size_t)b_0 * KC + i) * MC + m_0;
        const size_t o1 = ((size_t)b_1 * KC + i) * MC + m_1;
        c_prob[o0] = pp0; c_hard[o0] = (float)s0;
        c_prob[o1] = pp1; c_hard[o1] = (float)s1;

        const int wi = i >> 5; const unsigned sh = (unsigned)(i & 31);
#pragma unroll
        for (int w = 0; w < 4; w++)
            if (w == wi) { cb0[w] |= (s0 << sh); cb1[w] |= (s1 << sh); }

        __syncthreads();   // protect smem before next step's staging
    }

    // publish packed bits for the head
    ((uint4*)g_cbits)[p0] = make_uint4(cb0[0], cb0[1], cb0[2], cb0[3]);
    ((uint4*)g_cbits)[p1] = make_uint4(cb1[0], cb1[1], cb1[2], cb1[3]);
}

// ---------------- fused head (R8-proven) ----------------
#define HEAD_ROW 256
#define HEAD_SMEM (112 * HEAD_ROW * 4 + 400 * 4 + 8 * 128 * 8)
__global__ void __launch_bounds__(256) head_fused(
    const float* __restrict__ hW, const float* __restrict__ hb,
    float* __restrict__ yp)
{
    extern __shared__ __align__(16) float hsm[];
    float*    Wsh   = hsm;                                    // 112 x 256
    unsigned* bitsS = (unsigned*)(hsm + 112 * HEAD_ROW);      // 100 x 4
    unsigned long long* psum = (unsigned long long*)(bitsS + 400);  // 8 warps x 128

    const int b = blockIdx.x, tid = threadIdx.x;
    const int w = tid >> 5, lane = tid & 31;

    for (int l = tid; l < 112 * 50; l += 256) {
        int k = l / 50, q = l - k * 50;
        *(float4*)&Wsh[k * HEAD_ROW + 4 * q] = *(const float4*)&hW[k * 200 + 4 * q];
    }
    for (int l = tid; l < 112 * 14; l += 256) {
        int k = l / 14, q = l - k * 14;
        *(float4*)&Wsh[k * HEAD_ROW + 200 + 4 * q] = make_float4(0.f, 0.f, 0.f, 0.f);
    }
    for (int l = tid; l < 400; l += 256)
        bitsS[l] = g_cbits[(size_t)b * 400 + l];
    __syncthreads();

    unsigned long long zinit[4];
#pragma unroll
    for (int q = 0; q < 4; q++) {
        int o2 = lane + 32 * q;
        float lo = (2 * o2     < NOUTC) ? hb[2 * o2]     : -1e30f;
        float hi = (2 * o2 + 1 < NOUTC) ? hb[2 * o2 + 1] : -1e30f;
        asm("mov.b64 %0, {%1, %2};" : "=l"(zinit[q]) : "r"(__float_as_uint(lo)), "r"(__float_as_uint(hi)));
    }

    float macc[8];
#pragma unroll
    for (int q = 0; q < 8; q++) macc[q] = 0.f;

    for (int m = w; m < MC; m += 8) {
        unsigned long long z2[4];
#pragma unroll
        for (int q = 0; q < 4; q++) z2[q] = zinit[q];

#pragma unroll
        for (int wd = 0; wd < 4; wd++) {
            unsigned bits = bitsS[m * 4 + wd];
            const float* wbase = Wsh + (size_t)wd * 32 * HEAD_ROW;
            while (bits) {
                int t = __ffs(bits) - 1;
                bits &= bits - 1u;
                const unsigned long long* krow =
                    (const unsigned long long*)(wbase + (size_t)t * HEAD_ROW) + lane;
#pragma unroll
                for (int q = 0; q < 4; q++) {
                    asm("add.rn.f32x2 %0, %0, %1;" : "+l"(z2[q]) : "l"(krow[32 * q]));
                }
            }
        }

        float zz[8];
#pragma unroll
        for (int q = 0; q < 4; q++) {
            unsigned lo, hi;
            asm("mov.b64 {%0, %1}, %2;" : "=r"(lo), "=r"(hi) : "l"(z2[q]));
            zz[2 * q] = __uint_as_float(lo); zz[2 * q + 1] = __uint_as_float(hi);
        }
        float mx = zz[0];
#pragma unroll
        for (int q = 1; q < 8; q++) mx = fmaxf(mx, zz[q]);
#pragma unroll
        for (int s = 16; s; s >>= 1) mx = fmaxf(mx, __shfl_xor_sync(0xffffffffu, mx, s));
        float sum = 0.f;
#pragma unroll
        for (int q = 0; q < 8; q++) { zz[q] = expf(zz[q] - mx); sum += zz[q]; }
#pragma unroll
        for (int s = 16; s; s >>= 1) sum += __shfl_xor_sync(0xffffffffu, sum, s);
        float r = 1.f / sum;
#pragma unroll
        for (int q = 0; q < 8; q++) macc[q] = fmaf(zz[q], r, macc[q]);
    }

#pragma unroll
    for (int q = 0; q < 4; q++) {
        unsigned long long pk;
        asm("mov.b64 %0, {%1, %2};" : "=l"(pk)
            : "r"(__float_as_uint(macc[2 * q])), "r"(__float_as_uint(macc[2 * q + 1])));
        psum[w * 128 + lane + 32 * q] = pk;
    }
    __syncthreads();
    if (tid < 100) {
        float slo = 0.f, shi = 0.f;
#pragma unroll
        for (int ww = 0; ww < 8; ww++) {
            unsigned lo, hi;
            asm("mov.b64 {%0, %1}, %2;" : "=r"(lo), "=r"(hi) : "l"(psum[ww * 128 + tid]));
            slo += __uint_as_float(lo); shi += __uint_as_float(hi);
        }
        yp[(size_t)b * NOUTC + 2 * tid]     = logf(slo * (1.f / MC) + 1e-6f);
        yp[(size_t)b * NOUTC + 2 * tid + 1] = logf(shi * (1.f / MC) + 1e-6f);
    }
}

// ---------------- launch ----------------
extern "C" void kernel_launch(void* const* d_in, const int* in_sizes, int n_in,
                              void* d_out, int out_size) {
    const float* x     = (const float*)d_in[0];
    const float* Win   = (const float*)d_in[1];
    const float* binp  = (const float*)d_in[2];
    const float* Wh    = (const float*)d_in[3];
    const float* bh    = (const float*)d_in[4];
    const float* Wout  = (const float*)d_in[5];
    const float* bout  = (const float*)d_in[6];
    const float* pW1   = (const float*)d_in[7];
    const float* pb1   = (const float*)d_in[8];
    const float* pW2   = (const float*)d_in[9];
    const float* pb2   = (const float*)d_in[10];
    const float* hW    = (const float*)d_in[11];
    const float* hb    = (const float*)d_in[12];

    float* out    = (float*)d_out;
    float* c_prob = out;
    float* ypred  = out + (size_t)BN * KC * MC;
    float* c_hard = ypred + (size_t)BN * NOUTC;

    float *h0, *h1, *inter, *base;
    cudaGetSymbolAddress((void**)&h0,    g_h0);
    cudaGetSymbolAddress((void**)&h1,    g_h1);
    cudaGetSymbolAddress((void**)&inter, g_inter);
    cudaGetSymbolAddress((void**)&base,  g_base);

    cudaFuncSetAttribute(head_fused, cudaFuncAttributeMaxDynamicSharedMemorySize, HEAD_SMEM);

    init_kernel<<<1, 32>>>();

    // encoder: 128x64 tiles (bit-identical per-element fmaf k-chain)
    sgemm_v3<<<dim3(NHID/64, BN/128, 1), 256>>>(x,  Win, binp, h0, BN, NHID, CIN,  1);
    sgemm_v3<<<dim3(NHID/64, BN/128, 1), 256>>>(h0, Wh + 0*NHID*NHID, bh + 0*NHID, h1, BN, NHID, NHID, 1);
    sgemm_v3<<<dim3(NHID/64, BN/128, 1), 256>>>(h1, Wh + 1*NHID*NHID, bh + 1*NHID, h0, BN, NHID, NHID, 1);
    sgemm_v3<<<dim3(NHID/64, BN/128, 1), 256>>>(h0, Wh + 2*NHID*NHID, bh + 2*NHID, h1, BN, NHID, NHID, 1);
    sgemm_v3<<<dim3(NHID/64, BN/128, 1), 256>>>(h1, Wh + 3*NHID*NHID, bh + 3*NHID, h0, BN, NHID, NHID, 1);
    sgemm_v3<<<dim3(2, BN/128, 1), 256>>>(h0, Wout, bout, inter, BN, NF, NHID, 0);

    // all base vectors: base[i] = inter @ W1[i][:NF] + b1[i]  (batched over i)
    sgemm_v2<<<dim3(1, BN/64, KC), 256>>>(inter, pW1, pb1, base, BN, NL, NF, 0,
                                          (long)(NF + KC) * NL, NL, (long)BN * NL);

    // all 112 concept steps in one kernel (two-pass h-split, bit-exact)
    steps_fused<<<(BN * MC) / 256, 128>>>(pW1, pW2, pb2, c_prob, c_hard);

    // fused head: logits -> softmax -> mean -> log
    head_fused<<<BN, 256, HEAD_SMEM>>>(hW, hb, ypred);
}